// round 17
// baseline (speedup 1.0000x reference)
#include <cuda_runtime.h>
#include <cuda_bf16.h>
#include <cstdint>

// LayerHypercube: out[b, f*1024+o] = sum_j x[b, o^(1<<j)] * w[f,j,o] + bias[f,o] + x[b,o]
// B=2048, F=16, O=IN=1024, BITS=10. fm[f,j,o] == o^(1<<j) (computed, not loaded).
//
// R17 = R16 (persistent 592-block grid, 2o x 4fm, phase-cooperative staging,
//            f32x2 math, __stcs stores)
//   + row-interleaved staging: each chunk lane slot = [pA(8B) | qB(8B)], so
//     every gather (own, masks 1/2/4/8/16, chunks 1..4) is ONE LDS.128
//     serving both rows. No SHFL at all. ~60 fewer instr per pair.

#define BATCH   2048
#define INSZ    1024
#define OUTSZ   1024
#define NFM     16
#define NBITS   10

#define THREADS 128
#define NWARP   4
#define OTILE   64
#define OBLOCKS (OUTSZ / OTILE) // 16
#define BGRID   37              // 16*37 = 592 blocks = 148 SMs x 4 CTAs
#define TOTPAIRS (BATCH / 2)    // 1024 pairs per o-column
#define PPH     4               // pairs per phase (one per warp)
#define PH_MAX  7               // ceil(28/4); t_count is 27 or 28
#define NBUF    3               // phase buffers

#define CHUNK_B   512               // 32 lanes x 16B (A8|B8 interleaved)
#define PBUF_B    (5 * CHUNK_B)     // 2560 B per pair (5 chunks)
#define PHASE_B   (PPH * PBUF_B)    // 10240 B per phase

typedef unsigned long long ull;

__device__ __forceinline__ void cp8(uint32_t dst_smem, const void* src_gmem) {
    asm volatile("cp.async.ca.shared.global [%0], [%1], 8;\n"
                 :: "r"(dst_smem), "l"(src_gmem));
}
__device__ __forceinline__ void cp_commit() { asm volatile("cp.async.commit_group;\n"); }
__device__ __forceinline__ void cp_wait1()  { asm volatile("cp.async.wait_group 1;\n"); }

__device__ __forceinline__ void fma2(ull& d, ull a, ull b) {
    asm("fma.rn.f32x2 %0, %1, %2, %0;" : "+l"(d) : "l"(a), "l"(b));
}
__device__ __forceinline__ ull add2(ull a, ull b) {
    ull d; asm("add.rn.f32x2 %0, %1, %2;" : "=l"(d) : "l"(a), "l"(b)); return d;
}
__device__ __forceinline__ ull pk(float lo, float hi) {
    ull d; asm("mov.b64 %0, {%1, %2};" : "=l"(d) : "f"(lo), "f"(hi)); return d;
}
__device__ __forceinline__ void stcs1(void* p, ull v) {
    asm volatile("st.global.cs.b64 [%0], %1;" :: "l"(p), "l"(v));
}

__global__ __launch_bounds__(THREADS, 4)
void hypercube_kernel(const float* __restrict__ x,
                      const float* __restrict__ w,
                      const float* __restrict__ bias,
                      float* __restrict__ out)
{
    __shared__ float4 sbuf[NBUF * (PHASE_B / 16)];   // 30720 B

    const int tid   = threadIdx.x;
    const int lane  = tid & 31;
    const int wid   = tid >> 5;
    const int o2    = lane;            // o-pair index within the tile (0..31)
    const int fq    = wid;             // fm quad: fm = 4*fq + m
    const int by    = blockIdx.y;      // 0..36
    const int B0    = blockIdx.x * OTILE;
    const int ob2   = B0 + o2 * 2;     // this thread's o base (2 consecutive o)

    const int t_count = (TOTPAIRS - by + BGRID - 1) / BGRID;   // 27 or 28

    // ---- weights & bias -> registers as f32x2 (loaded once per block) ----
    ull wf[4][NBITS];
    ull bb[4];
#pragma unroll
    for (int m = 0; m < 4; m++) {
        const int fm = 4 * fq + m;
#pragma unroll
        for (int j = 0; j < NBITS; j++)
            wf[m][j] = *reinterpret_cast<const ull*>(w + ((fm * NBITS + j) * OUTSZ + ob2));
        bb[m] = *reinterpret_cast<const ull*>(bias + fm * OUTSZ + ob2);
    }

    // ---- staging: per pair, 5 chunks x 32 lanes x (A 8B + B 8B) ----
    // lane's gmem byte offset for chunk k within a row: (tb ^ xorB_k) + lane*8
    int srcOff[5];
    {
        const int tb = B0 * 4;   // tile byte offset within a row
        srcOff[0] = tb + lane * 8;
        srcOff[1] = (tb ^ 256)  + lane * 8;
        srcOff[2] = (tb ^ 512)  + lane * 8;
        srcOff[3] = (tb ^ 1024) + lane * 8;
        srcOff[4] = (tb ^ 2048) + lane * 8;
    }

    const uint32_t sbase = (uint32_t)__cvta_generic_to_shared(sbuf);
    const char*    xb    = reinterpret_cast<const char*>(x);

    // warp wid stages work-item t = ph*4 + wid (pair index by + 37*t)
    auto issue_phase = [&](int ph) {
        const int t = ph * PPH + wid;
        if (t < t_count) {
            const char* base = xb + (size_t)(by + BGRID * t) * 8192;
            const uint32_t db = sbase + (ph % NBUF) * PHASE_B + wid * PBUF_B + lane * 16;
#pragma unroll
            for (int k = 0; k < 5; k++) {
                cp8(db + k * CHUNK_B,     base + srcOff[k]);          // row A
                cp8(db + k * CHUNK_B + 8, base + 4096 + srcOff[k]);   // row B
            }
        }
    };

    issue_phase(0); cp_commit();
    issue_phase(1); cp_commit();

    float* opBase = out + (size_t)(2 * by) * (NFM * OUTSZ) + (4 * fq) * OUTSZ + ob2;
    const size_t OP_T = (size_t)(2 * BGRID) * (NFM * OUTSZ);   // out stride per t

    for (int ph = 0; ph < PH_MAX; ph++) {
        cp_wait1();            // this warp's copies for phase ph complete
        __syncthreads();       // all warps' copies complete; phase ph-1 reads done

        issue_phase(ph + 2);   // internally bounded by t_count
        cp_commit();           // uniform group accounting

        const char* pb = reinterpret_cast<const char*>(sbuf) + (ph % NBUF) * PHASE_B;

#pragma unroll
        for (int i = 0; i < PPH; i++) {
            const int t = ph * PPH + i;
            if (t >= t_count) break;

            const char* rb = pb + i * PBUF_B;

            // ALL gathers: one LDS.128 each, all independent.
            const float4 own = *reinterpret_cast<const float4*>(rb + o2 * 16);
            const ulonglong2 G1  = *reinterpret_cast<const ulonglong2*>(rb + (o2 ^ 1)  * 16);
            const ulonglong2 G2  = *reinterpret_cast<const ulonglong2*>(rb + (o2 ^ 2)  * 16);
            const ulonglong2 G4  = *reinterpret_cast<const ulonglong2*>(rb + (o2 ^ 4)  * 16);
            const ulonglong2 G8  = *reinterpret_cast<const ulonglong2*>(rb + (o2 ^ 8)  * 16);
            const ulonglong2 G16 = *reinterpret_cast<const ulonglong2*>(rb + (o2 ^ 16) * 16);
            const ulonglong2 H6  = *reinterpret_cast<const ulonglong2*>(rb + 1 * CHUNK_B + o2 * 16);
            const ulonglong2 H7  = *reinterpret_cast<const ulonglong2*>(rb + 2 * CHUNK_B + o2 * 16);
            const ulonglong2 H8  = *reinterpret_cast<const ulonglong2*>(rb + 3 * CHUNK_B + o2 * 16);
            const ulonglong2 H9  = *reinterpret_cast<const ulonglong2*>(rb + 4 * CHUNK_B + o2 * 16);

            const ull P   = pk(own.x, own.y), Q   = pk(own.z, own.w);
            const ull Psw = pk(own.y, own.x), Qsw = pk(own.w, own.z);

            // acc = bias + tiled x ; j=0 uses swapped own pair
            ull a[4], c[4];
#pragma unroll
            for (int m = 0; m < 4; m++) {
                a[m] = add2(bb[m], P);
                c[m] = add2(bb[m], Q);
                fma2(a[m], wf[m][0], Psw);
                fma2(c[m], wf[m][0], Qsw);
            }

            // j=1..5 from the mask gathers; j=6..9 from remote chunks
#pragma unroll
            for (int m = 0; m < 4; m++) {
                fma2(a[m], wf[m][1], G1.x);   fma2(c[m], wf[m][1], G1.y);
                fma2(a[m], wf[m][2], G2.x);   fma2(c[m], wf[m][2], G2.y);
                fma2(a[m], wf[m][3], G4.x);   fma2(c[m], wf[m][3], G4.y);
                fma2(a[m], wf[m][4], G8.x);   fma2(c[m], wf[m][4], G8.y);
                fma2(a[m], wf[m][5], G16.x);  fma2(c[m], wf[m][5], G16.y);
                fma2(a[m], wf[m][6], H6.x);   fma2(c[m], wf[m][6], H6.y);
                fma2(a[m], wf[m][7], H7.x);   fma2(c[m], wf[m][7], H7.y);
                fma2(a[m], wf[m][8], H8.x);   fma2(c[m], wf[m][8], H8.y);
                fma2(a[m], wf[m][9], H9.x);   fma2(c[m], wf[m][9], H9.y);
            }

            // stores: 8 x STG.64, perfectly coalesced across the warp
            float* op = opBase + (size_t)t * OP_T;
#pragma unroll
            for (int m = 0; m < 4; m++) {
                stcs1(op + m * OUTSZ,               a[m]);
                stcs1(op + NFM * OUTSZ + m * OUTSZ, c[m]);
            }
        }
    }
}

extern "C" void kernel_launch(void* const* d_in, const int* in_sizes, int n_in,
                              void* d_out, int out_size)
{
    const float* x    = (const float*)d_in[0];
    const float* w    = (const float*)d_in[1];
    const float* bias = (const float*)d_in[2];
    // d_in[3] = fm (int32) — values are o^(1<<j), computed inline instead.
    float* out = (float*)d_out;

    dim3 grid(OBLOCKS, BGRID);
    hypercube_kernel<<<grid, THREADS>>>(x, w, bias, out);
}